// round 11
// baseline (speedup 1.0000x reference)
#include <cuda_runtime.h>
#include <cuda_fp16.h>

#define N_USERS 200000
#define N_SPOTS 50000
#define N_TOT   (N_USERS + N_SPOTS)
#define D 64
#define DV 16           // D/4: float4 per f32 row, uint2 (4 halves) per h16 row
#define MAX_E 3200000
#define CHUNK 512
#define NBLK ((N_TOT + CHUNK - 1) / CHUNK)   // 489

// ---------------- __device__ scratch (no allocations allowed) ----------------
__device__ int   g_deg[N_TOT];                 // zeroed per call
__device__ unsigned long long g_tile[NBLK];    // scan descriptors, zeroed per call
__device__ float g_inv[N_TOT];
__device__ int   g_start[N_TOT + 1];
__device__ int   g_cur[N_TOT];
__device__ int   g_adj[2 * MAX_E];   // user adjacency in [0,E), spot in [E,2E)
__device__ uint2 g_user_h[N_USERS * DV];  // prescaled user msgs, fp16
__device__ uint2 g_spot_h[N_SPOTS * DV];  // prescaled spot msgs, fp16

// ---------------- degree count (combined) ----------------
__global__ void degree_kernel(const int* __restrict__ ui,
                              const int* __restrict__ si, int E) {
    int e = blockIdx.x * blockDim.x + threadIdx.x;
    if (e < E) {
        atomicAdd(&g_deg[ui[e]], 1);
        atomicAdd(&g_deg[N_USERS + si[e]], 1);
    }
}

// ---------------- single-pass scan: decoupled lookback ----------------------
// status 1 = aggregate available, 2 = inclusive prefix available.
__device__ __forceinline__ unsigned long long pack_ts(int status, int val) {
    return ((unsigned long long)(unsigned)status << 32) | (unsigned)val;
}

__global__ void scan_kernel(int total_all) {
    __shared__ int sm[CHUNK];
    __shared__ int s_prefix;
    int bid = blockIdx.x, t = threadIdx.x;
    int i = bid * CHUNK + t;
    int v = (i < N_TOT) ? g_deg[i] : 0;
    if (i < N_TOT) g_inv[i] = rsqrtf(v ? (float)v : 1e-6f);
    sm[t] = v;
    __syncthreads();
    for (int off = 1; off < CHUNK; off <<= 1) {
        int x = (t >= off) ? sm[t - off] : 0;
        __syncthreads();
        sm[t] += x;
        __syncthreads();
    }
    int total = sm[CHUNK - 1];

    if (t < 32) {
        if (bid == 0) {
            if (t == 0) {
                atomicExch(&g_tile[0], pack_ts(2, total));
                s_prefix = 0;
            }
        } else {
            if (t == 0) atomicExch(&g_tile[bid], pack_ts(1, total));
            // warp-parallel lookback, window of 32 predecessors
            int running = 0;
            int tilej = bid - 1;
            while (true) {
                int j = tilej - t;
                int f, val;
                if (j >= 0) {
                    unsigned long long p;
                    do { p = atomicAdd(&g_tile[j], 0ULL); } while ((p >> 32) == 0);
                    f = (int)(p >> 32);
                    val = (int)(p & 0xFFFFFFFFULL);
                } else { f = 2; val = 0; }
                unsigned ball = __ballot_sync(0xFFFFFFFFu, f == 2);
                int contrib;
                if (ball) {
                    int first = __ffs(ball) - 1;  // nearest block with inclusive
                    contrib = (t <= first) ? val : 0;
                } else {
                    contrib = val;  // all aggregates: take whole window
                }
#pragma unroll
                for (int o = 16; o > 0; o >>= 1)
                    contrib += __shfl_down_sync(0xFFFFFFFFu, contrib, o);
                contrib = __shfl_sync(0xFFFFFFFFu, contrib, 0);
                running += contrib;
                if (ball) break;
                tilej -= 32;
            }
            if (t == 0) {
                atomicExch(&g_tile[bid], pack_ts(2, running + total));
                s_prefix = running;
            }
        }
    }
    __syncthreads();
    if (i < N_TOT) {
        int ex = s_prefix + sm[t] - v;
        g_start[i] = ex;
        g_cur[i]   = ex;
    }
    if (i == 0) g_start[N_TOT] = total_all;
}

// ---------------- fused fill (cursor atomics) + prescale --------------------
__global__ void fill_prescale_kernel(const int* __restrict__ ui,
                                     const int* __restrict__ si,
                                     const float4* __restrict__ ux,
                                     const float4* __restrict__ sx,
                                     int E, int nb_fill) {
    if ((int)blockIdx.x < nb_fill) {
        int e = blockIdx.x * blockDim.x + threadIdx.x;
        if (e < E) {
            int u = ui[e], s = si[e];
            int pu = atomicAdd(&g_cur[u], 1);
            g_adj[pu] = s;
            int ps = atomicAdd(&g_cur[N_USERS + s], 1);
            g_adj[ps] = u;
        }
    } else {
        int i = (blockIdx.x - nb_fill) * blockDim.x + threadIdx.x;
        const int nU = N_USERS * DV;
        const int nS = N_SPOTS * DV;
        if (i < nU) {
            float m = g_inv[i >> 4];
            float4 v = ux[i];
            __half2 h0 = __floats2half2_rn(v.x * m, v.y * m);
            __half2 h1 = __floats2half2_rn(v.z * m, v.w * m);
            uint2 p;
            p.x = *reinterpret_cast<unsigned*>(&h0);
            p.y = *reinterpret_cast<unsigned*>(&h1);
            g_user_h[i] = p;
        } else if (i < nU + nS) {
            int j = i - nU;
            float m = g_inv[N_USERS + (j >> 4)];
            float4 v = sx[j];
            __half2 h0 = __floats2half2_rn(v.x * m, v.y * m);
            __half2 h1 = __floats2half2_rn(v.z * m, v.w * m);
            uint2 p;
            p.x = *reinterpret_cast<unsigned*>(&h0);
            p.y = *reinterpret_cast<unsigned*>(&h1);
            g_spot_h[j] = p;
        }
    }
}

// ---------------- pull body: out[n] = inv_dst[n] * sum_nbr msg_h16[nbr] -----
// 16 lanes per node, one uint2 (4 halves = 8B) per lane -> 128B row = 1 wf.
// Dual accumulators break the FADD dependency chain; the last partial batch is
// a predicated fully-unrolled pass (rem uniform per 16-lane group).
__device__ __forceinline__ void pull_node(const uint2* __restrict__ src,
                                          const int* __restrict__ start,
                                          const float* __restrict__ inv_dst,
                                          float4* __restrict__ out,
                                          int node, int lane, unsigned mask) {
    int b = start[node];
    int e = start[node + 1];
    float m = inv_dst[node];
    float4 a0 = make_float4(0.f, 0.f, 0.f, 0.f);
    float4 a1 = make_float4(0.f, 0.f, 0.f, 0.f);
    for (int base = b; base < e; base += 16) {
        int rem = e - base;  // uniform within the 16-lane group
        int idx = (lane < rem) ? __ldg(&g_adj[base + lane]) : 0;
#pragma unroll
        for (int k = 0; k < 16; k += 2) {
            if (k < rem) {
                int s = __shfl_sync(mask, idx, k, 16);
                uint2 p = __ldg(&src[s * DV + lane]);
                float2 f0 = __half22float2(*reinterpret_cast<__half2*>(&p.x));
                float2 f1 = __half22float2(*reinterpret_cast<__half2*>(&p.y));
                a0.x += f0.x; a0.y += f0.y; a0.z += f1.x; a0.w += f1.y;
            }
            if (k + 1 < rem) {
                int s = __shfl_sync(mask, idx, k + 1, 16);
                uint2 p = __ldg(&src[s * DV + lane]);
                float2 f0 = __half22float2(*reinterpret_cast<__half2*>(&p.x));
                float2 f1 = __half22float2(*reinterpret_cast<__half2*>(&p.y));
                a1.x += f0.x; a1.y += f0.y; a1.z += f1.x; a1.w += f1.y;
            }
        }
    }
    float4 acc;
    acc.x = (a0.x + a1.x) * m;
    acc.y = (a0.y + a1.y) * m;
    acc.z = (a0.z + a1.z) * m;
    acc.w = (a0.w + a1.w) * m;
    out[node * DV + lane] = acc;
}

// ---------------- fused pulls (both directions in one grid) -----------------
__global__ void pull_all_kernel(float4* __restrict__ out_user,
                                float4* __restrict__ out_spot,
                                int nb_user) {
    int lane = threadIdx.x & 15;
    unsigned mask = 0xFFFFu << (threadIdx.x & 16);
    int grp = threadIdx.x >> 4;  // 0..15
    if ((int)blockIdx.x < nb_user) {
        int node = blockIdx.x * 16 + grp;
        if (node < N_USERS)
            pull_node(g_spot_h, g_start, g_inv, out_user, node, lane, mask);
    } else {
        int node = (blockIdx.x - nb_user) * 16 + grp;
        if (node < N_SPOTS)
            pull_node(g_user_h, g_start + N_USERS, g_inv + N_USERS,
                      out_spot, node, lane, mask);
    }
}

extern "C" void kernel_launch(void* const* d_in, const int* in_sizes, int n_in,
                              void* d_out, int out_size) {
    const float4* ux = (const float4*)d_in[0];   // user_x [N_USERS, D]
    const float4* sx = (const float4*)d_in[1];   // spot_x [N_SPOTS, D]
    const int* ui = (const int*)d_in[2];         // user_idx [E]
    const int* si = (const int*)d_in[3];         // spot_idx [E]
    int E = in_sizes[2];

    float* out = (float*)d_out;
    float4* out_user = (float4*)out;                          // [N_USERS, D]
    float4* out_spot = (float4*)(out + (size_t)N_USERS * D);  // [N_SPOTS, D]

    int* p_deg;
    unsigned long long* p_tile;
    cudaGetSymbolAddress((void**)&p_deg, g_deg);
    cudaGetSymbolAddress((void**)&p_tile, g_tile);

    cudaMemsetAsync(p_deg, 0, N_TOT * sizeof(int));
    cudaMemsetAsync(p_tile, 0, NBLK * sizeof(unsigned long long));

    degree_kernel<<<(E + 255) / 256, 256>>>(ui, si, E);

    scan_kernel<<<NBLK, CHUNK>>>(2 * E);

    int nb_fill = (E + 255) / 256;                        // 12500
    int nb_pre  = ((N_USERS + N_SPOTS) * DV + 255) / 256; // 15625
    fill_prescale_kernel<<<nb_fill + nb_pre, 256>>>(ui, si, ux, sx, E, nb_fill);

    int nb_user = (N_USERS + 15) / 16;  // 12500
    int nb_spot = (N_SPOTS + 15) / 16;  // 3125
    pull_all_kernel<<<nb_user + nb_spot, 256>>>(out_user, out_spot, nb_user);
}

// round 12
// speedup vs baseline: 1.2516x; 1.2516x over previous
#include <cuda_runtime.h>
#include <cuda_fp16.h>

#define N_USERS 200000
#define N_SPOTS 50000
#define D 64
#define DV 16           // D/4: float4 per f32 row, uint2 (4 halves) per h16 row
#define DV8 8           // D/8: uint4 (8 halves) per h16 row
#define MAX_E 3200000
#define CHUNK 512
#define NCHUNK_U ((N_USERS + CHUNK - 1) / CHUNK)   // 391
#define NCHUNK_S ((N_SPOTS + CHUNK - 1) / CHUNK)   // 98

// ---------------- __device__ scratch (no allocations allowed) ----------------
__device__ int   g_deg_user[N_USERS];
__device__ int   g_deg_spot[N_SPOTS];
__device__ float g_inv_user[N_USERS];
__device__ float g_inv_spot[N_SPOTS];
__device__ int   g_start_user[N_USERS + 1];
__device__ int   g_start_spot[N_SPOTS + 1];
__device__ int   g_cur_user[N_USERS];
__device__ int   g_cur_spot[N_SPOTS];
__device__ int   g_adj_user[MAX_E];   // spot neighbors grouped by user
__device__ int   g_adj_spot[MAX_E];   // user neighbors grouped by spot
__device__ int   g_csum_user[CHUNK];  // chunk partial sums (391 used)
__device__ int   g_csum_spot[CHUNK];  // (98 used)
__device__ uint2 g_user_h[N_USERS * DV];  // prescaled user msgs, fp16 (8B/lane)
__device__ uint2 g_spot_h[N_SPOTS * DV];  // prescaled spot msgs, fp16

// ---------------- degree count ----------------
__global__ void degree_kernel(const int* __restrict__ ui,
                              const int* __restrict__ si, int E) {
    int e = blockIdx.x * blockDim.x + threadIdx.x;
    if (e < E) {
        atomicAdd(&g_deg_user[ui[e]], 1);
        atomicAdd(&g_deg_spot[si[e]], 1);
    }
}

// ---------------- scan phase 1 (both sides): per-chunk sums + fused rsqrt ---
__global__ void chunk_sum_all_kernel() {
    __shared__ int sm[CHUNK];
    const int* deg;  int* sums;  float* inv;  int n, cb;
    if (blockIdx.x < NCHUNK_U) {
        deg = g_deg_user; sums = g_csum_user; inv = g_inv_user;
        n = N_USERS; cb = blockIdx.x;
    } else {
        deg = g_deg_spot; sums = g_csum_spot; inv = g_inv_spot;
        n = N_SPOTS; cb = blockIdx.x - NCHUNK_U;
    }
    int i = cb * CHUNK + threadIdx.x;
    int v = (i < n) ? deg[i] : 0;
    sm[threadIdx.x] = v;
    if (i < n) inv[i] = rsqrtf(v ? (float)v : 1e-6f);
    __syncthreads();
    for (int off = CHUNK / 2; off > 0; off >>= 1) {
        if (threadIdx.x < off) sm[threadIdx.x] += sm[threadIdx.x + off];
        __syncthreads();
    }
    if (threadIdx.x == 0) sums[cb] = sm[0];
}

// ---------------- scan phase 2: exclusive scan of both chunk-sum arrays -----
__global__ void scan_sums_all_kernel() {
    __shared__ int sm[CHUNK];
    int t = threadIdx.x;
    // user side
    {
        int v = (t < NCHUNK_U) ? g_csum_user[t] : 0;
        sm[t] = v;
        __syncthreads();
        for (int off = 1; off < CHUNK; off <<= 1) {
            int x = (t >= off) ? sm[t - off] : 0;
            __syncthreads();
            sm[t] += x;
            __syncthreads();
        }
        if (t < NCHUNK_U) g_csum_user[t] = sm[t] - v;
        __syncthreads();
    }
    // spot side
    {
        int v = (t < NCHUNK_S) ? g_csum_spot[t] : 0;
        sm[t] = v;
        __syncthreads();
        for (int off = 1; off < CHUNK; off <<= 1) {
            int x = (t >= off) ? sm[t - off] : 0;
            __syncthreads();
            sm[t] += x;
            __syncthreads();
        }
        if (t < NCHUNK_S) g_csum_spot[t] = sm[t] - v;
    }
}

// ---------------- scan phase 3 (both sides): chunk scan -> start + cursor ---
__global__ void chunk_scan_all_kernel(int E) {
    __shared__ int sm[CHUNK];
    const int* deg;  const int* coff;  int* start;  int* cur;  int n, cb;
    if (blockIdx.x < NCHUNK_U) {
        deg = g_deg_user; coff = g_csum_user; start = g_start_user;
        cur = g_cur_user; n = N_USERS; cb = blockIdx.x;
    } else {
        deg = g_deg_spot; coff = g_csum_spot; start = g_start_spot;
        cur = g_cur_spot; n = N_SPOTS; cb = blockIdx.x - NCHUNK_U;
    }
    int i = cb * CHUNK + threadIdx.x;
    int t = threadIdx.x;
    int v = (i < n) ? deg[i] : 0;
    sm[t] = v;
    __syncthreads();
    for (int off = 1; off < CHUNK; off <<= 1) {
        int x = (t >= off) ? sm[t - off] : 0;
        __syncthreads();
        sm[t] += x;
        __syncthreads();
    }
    if (i < n) {
        int ex = coff[cb] + sm[t] - v;
        start[i] = ex;
        cur[i]   = ex;
    }
    if (i == 0) start[n] = E;
}

// ---------------- fused fill (cursor atomics) + prescale --------------------
__global__ void fill_prescale_kernel(const int* __restrict__ ui,
                                     const int* __restrict__ si,
                                     const float4* __restrict__ ux,
                                     const float4* __restrict__ sx,
                                     int E, int nb_fill) {
    if ((int)blockIdx.x < nb_fill) {
        int e = blockIdx.x * blockDim.x + threadIdx.x;
        if (e < E) {
            int u = ui[e], s = si[e];
            int pu = atomicAdd(&g_cur_user[u], 1);
            g_adj_user[pu] = s;
            int ps = atomicAdd(&g_cur_spot[s], 1);
            g_adj_spot[ps] = u;
        }
    } else {
        int i = (blockIdx.x - nb_fill) * blockDim.x + threadIdx.x;
        const int nU = N_USERS * DV;
        const int nS = N_SPOTS * DV;
        if (i < nU) {
            float m = g_inv_user[i >> 4];
            float4 v = ux[i];
            __half2 h0 = __floats2half2_rn(v.x * m, v.y * m);
            __half2 h1 = __floats2half2_rn(v.z * m, v.w * m);
            uint2 p;
            p.x = *reinterpret_cast<unsigned*>(&h0);
            p.y = *reinterpret_cast<unsigned*>(&h1);
            g_user_h[i] = p;
        } else if (i < nU + nS) {
            int j = i - nU;
            float m = g_inv_spot[j >> 4];
            float4 v = sx[j];
            __half2 h0 = __floats2half2_rn(v.x * m, v.y * m);
            __half2 h1 = __floats2half2_rn(v.z * m, v.w * m);
            uint2 p;
            p.x = *reinterpret_cast<unsigned*>(&h0);
            p.y = *reinterpret_cast<unsigned*>(&h1);
            g_spot_h[j] = p;
        }
    }
}

// ---------------- pull body: out[n] = inv_dst[n] * sum_nbr msg_h16[nbr] -----
// 8 lanes per node, one uint4 (8 halves = 16B) per lane -> 128B row = 1 L1
// wavefront per neighbor, and each warp LDG/SHFL now serves 4 nodes (was 2).
// a0 holds cols {0..3}+8*lane, a1 cols {4..7}+8*lane: dual chains for ILP.
__device__ __forceinline__ void pull_node(const uint4* __restrict__ src,
                                          const int* __restrict__ adj,
                                          const int* __restrict__ start,
                                          const float* __restrict__ inv_dst,
                                          float4* __restrict__ out,
                                          int node, int lane, unsigned segmask) {
    int b = start[node];
    int e = start[node + 1];
    float m = inv_dst[node];
    float4 a0 = make_float4(0.f, 0.f, 0.f, 0.f);
    float4 a1 = make_float4(0.f, 0.f, 0.f, 0.f);
    int base = b;
    // full 8-neighbor batches, fully unrolled
    for (; base + 8 <= e; base += 8) {
        int idx = __ldg(&adj[base + lane]);
#pragma unroll
        for (int k = 0; k < 8; k++) {
            int s = __shfl_sync(segmask, idx, k, 8);
            uint4 p = __ldg(&src[s * DV8 + lane]);
            float2 f0 = __half22float2(*reinterpret_cast<__half2*>(&p.x));
            float2 f1 = __half22float2(*reinterpret_cast<__half2*>(&p.y));
            float2 f2 = __half22float2(*reinterpret_cast<__half2*>(&p.z));
            float2 f3 = __half22float2(*reinterpret_cast<__half2*>(&p.w));
            a0.x += f0.x; a0.y += f0.y; a0.z += f1.x; a0.w += f1.y;
            a1.x += f2.x; a1.y += f2.y; a1.z += f3.x; a1.w += f3.y;
        }
    }
    // remainder (rolled — no per-k predication)
    if (base < e) {
        int cnt = e - base;
        int idx = (base + lane < e) ? __ldg(&adj[base + lane]) : 0;
        for (int k = 0; k < cnt; k++) {
            int s = __shfl_sync(segmask, idx, k, 8);
            uint4 p = __ldg(&src[s * DV8 + lane]);
            float2 f0 = __half22float2(*reinterpret_cast<__half2*>(&p.x));
            float2 f1 = __half22float2(*reinterpret_cast<__half2*>(&p.y));
            float2 f2 = __half22float2(*reinterpret_cast<__half2*>(&p.z));
            float2 f3 = __half22float2(*reinterpret_cast<__half2*>(&p.w));
            a0.x += f0.x; a0.y += f0.y; a0.z += f1.x; a0.w += f1.y;
            a1.x += f2.x; a1.y += f2.y; a1.z += f3.x; a1.w += f3.y;
        }
    }
    a0.x *= m; a0.y *= m; a0.z *= m; a0.w *= m;
    a1.x *= m; a1.y *= m; a1.z *= m; a1.w *= m;
    out[node * DV + 2 * lane]     = a0;
    out[node * DV + 2 * lane + 1] = a1;
}

// ---------------- fused pulls (both directions in one grid) -----------------
__global__ void pull_all_kernel(float4* __restrict__ out_user,
                                float4* __restrict__ out_spot,
                                int nb_user) {
    int lane = threadIdx.x & 7;
    unsigned segmask = 0xFFu << (threadIdx.x & 24);
    int grp = threadIdx.x >> 3;  // 0..31
    if ((int)blockIdx.x < nb_user) {
        int node = blockIdx.x * 32 + grp;
        if (node < N_USERS)
            pull_node((const uint4*)g_spot_h, g_adj_user, g_start_user,
                      g_inv_user, out_user, node, lane, segmask);
    } else {
        int node = (blockIdx.x - nb_user) * 32 + grp;
        if (node < N_SPOTS)
            pull_node((const uint4*)g_user_h, g_adj_spot, g_start_spot,
                      g_inv_spot, out_spot, node, lane, segmask);
    }
}

extern "C" void kernel_launch(void* const* d_in, const int* in_sizes, int n_in,
                              void* d_out, int out_size) {
    const float4* ux = (const float4*)d_in[0];   // user_x [N_USERS, D]
    const float4* sx = (const float4*)d_in[1];   // spot_x [N_SPOTS, D]
    const int* ui = (const int*)d_in[2];         // user_idx [E]
    const int* si = (const int*)d_in[3];         // spot_idx [E]
    int E = in_sizes[2];

    float* out = (float*)d_out;
    float4* out_user = (float4*)out;                          // [N_USERS, D]
    float4* out_spot = (float4*)(out + (size_t)N_USERS * D);  // [N_SPOTS, D]

    int *p_deg_u, *p_deg_s;
    cudaGetSymbolAddress((void**)&p_deg_u, g_deg_user);
    cudaGetSymbolAddress((void**)&p_deg_s, g_deg_spot);

    cudaMemsetAsync(p_deg_u, 0, N_USERS * sizeof(int));
    cudaMemsetAsync(p_deg_s, 0, N_SPOTS * sizeof(int));

    degree_kernel<<<(E + 255) / 256, 256>>>(ui, si, E);

    chunk_sum_all_kernel<<<NCHUNK_U + NCHUNK_S, CHUNK>>>();
    scan_sums_all_kernel<<<1, CHUNK>>>();
    chunk_scan_all_kernel<<<NCHUNK_U + NCHUNK_S, CHUNK>>>(E);

    int nb_fill = (E + 255) / 256;                        // 12500
    int nb_pre  = ((N_USERS + N_SPOTS) * DV + 255) / 256; // 15625
    fill_prescale_kernel<<<nb_fill + nb_pre, 256>>>(ui, si, ux, sx, E, nb_fill);

    int nb_user = (N_USERS + 31) / 32;  // 6250
    int nb_spot = (N_SPOTS + 31) / 32;  // 1563
    pull_all_kernel<<<nb_user + nb_spot, 256>>>(out_user, out_spot, nb_user);
}